// round 6
// baseline (speedup 1.0000x reference)
#include <cuda_runtime.h>
#include <cuda_fp16.h>
#include <cstdint>

#define K_DIM 4096
#define N_DIM 4096
#define M_DIM 8192

#define BM 128
#define BN 256
#define BKC 64
#define NC (K_DIM / BKC)        // 64 chunks
#define THREADS 512

#define ROWB 144                // 64 halves (128B) + 16B pad per smem row
#define A_STAGE (BM * ROWB)     // 18432
#define B_STAGE (BN * ROWB)     // 36864
#define A_SM3 (3 * A_STAGE)     // 55296
#define SMEM_TOTAL (A_SM3 + 2 * B_STAGE)  // 129024

// x converted fp32 -> fp16 (exact: values originated as fp16).
__device__ __half g_X[(size_t)M_DIM * K_DIM];

__device__ __forceinline__ uint32_t smem_u32(const void* p) {
    return (uint32_t)__cvta_generic_to_shared(p);
}
__device__ __forceinline__ void cp_async16(uint32_t dst, const void* src) {
    asm volatile("cp.async.cg.shared.global [%0], [%1], 16;" :: "r"(dst), "l"(src));
}
__device__ __forceinline__ void ldmx4(uint32_t* r, uint32_t addr) {
    asm volatile("ldmatrix.sync.aligned.m8n8.x4.shared.b16 {%0,%1,%2,%3}, [%4];"
                 : "=r"(r[0]), "=r"(r[1]), "=r"(r[2]), "=r"(r[3]) : "r"(addr));
}
__device__ __forceinline__ void mma16816(float* c, const uint32_t* a, uint32_t b0, uint32_t b1) {
    asm volatile(
        "mma.sync.aligned.m16n8k16.row.col.f32.f16.f16.f32 "
        "{%0,%1,%2,%3}, {%4,%5,%6,%7}, {%8,%9}, {%0,%1,%2,%3};"
        : "+f"(c[0]), "+f"(c[1]), "+f"(c[2]), "+f"(c[3])
        : "r"(a[0]), "r"(a[1]), "r"(a[2]), "r"(a[3]), "r"(b0), "r"(b1));
}

// ---------------- Kernel 0: x fp32 -> fp16 ----------------
__global__ __launch_bounds__(256) void convert_x_kernel(const float* __restrict__ xf) {
    size_t i = ((size_t)blockIdx.x * blockDim.x + threadIdx.x) * 8;
    float4 v0 = *reinterpret_cast<const float4*>(xf + i);
    float4 v1 = *reinterpret_cast<const float4*>(xf + i + 4);
    __half h[8];
    h[0] = __float2half_rn(v0.x); h[1] = __float2half_rn(v0.y);
    h[2] = __float2half_rn(v0.z); h[3] = __float2half_rn(v0.w);
    h[4] = __float2half_rn(v1.x); h[5] = __float2half_rn(v1.y);
    h[6] = __float2half_rn(v1.z); h[7] = __float2half_rn(v1.w);
    *reinterpret_cast<uint4*>(&g_X[i]) = *reinterpret_cast<const uint4*>(h);
}

// ---------------- Kernel 1: fused dequant + GEMM ----------------
// CTA tile 128x256xK64, 512 threads, 16 warps = 2(M) x 8(N), warp tile 64x32.
// A: 3-stage cp.async. B: 4-bit qweight LDG -> unpack -> STS, 2-stage,
// two threads per output column (4 words each).
__global__ __launch_bounds__(THREADS, 1) void gemm_fused(const int* __restrict__ qw,
                                                         const float* __restrict__ scales,
                                                         const int* __restrict__ qz,
                                                         const float* __restrict__ biasf,
                                                         float* __restrict__ out) {
    extern __shared__ __align__(1024) char smem[];
    const uint32_t sbase = smem_u32(smem);
    const int tid = threadIdx.x;
    const int lane = tid & 31;
    const int warp = tid >> 5;
    const int warpM = warp & 1;   // 0..1
    const int warpN = warp >> 1;  // 0..7
    const int bm = blockIdx.y * BM;
    const int bn = blockIdx.x * BN;

    float acc[4][4][4];
#pragma unroll
    for (int i = 0; i < 4; i++)
#pragma unroll
        for (int j = 0; j < 4; j++)
#pragma unroll
            for (int e = 0; e < 4; e++) acc[i][j][e] = 0.0f;

    // ---- A loader: 128 rows x 128B = 1024 16B vectors per stage ----
    auto issueA = [&](int st, int c) {
#pragma unroll
        for (int i = 0; i < 2; i++) {
            int id = tid + i * THREADS;      // 0..1023
            int row = id >> 3;               // 0..127
            int v = id & 7;                  // 0..7
            uint32_t dst = sbase + st * A_STAGE + row * ROWB + v * 16;
            const __half* src = g_X + (size_t)(bm + row) * K_DIM + c * BKC + v * 8;
            cp_async16(dst, src);
        }
    };

    // ---- B loader: col = tid&255 owns n = bn+col; half = tid>>8 does 4 of the
    //      8 qweight words for this chunk. Double-buffered registers. ----
    const int colB = tid & 255;
    const int halfB = tid >> 8;              // 0 or 1
    const int n_own = bn + colB;
    int rw[2][4];
    float sbuf[2];
    int zbuf[2];
    auto ldgB = [&](int buf, int c) {
#pragma unroll
        for (int j = 0; j < 4; j++)
            rw[buf][j] = qw[(size_t)(c * 8 + halfB * 4 + j) * N_DIM + n_own];
        int g = c >> 1;                       // group = (c*64)/128
        sbuf[buf] = scales[g * N_DIM + n_own];
        zbuf[buf] = qz[g * (N_DIM / 8) + (n_own >> 3)];
    };
    auto stsB = [&](int buf, int bs) {
        __half s = __float2half_rn(sbuf[buf]);
        int z = ((zbuf[buf] >> ((n_own & 7) * 4)) & 0xF) + 1;
        char* base = smem + A_SM3 + bs * B_STAGE + colB * ROWB + halfB * 64;
#pragma unroll
        for (int i = 0; i < 4; i++) {
            __half vals[8];
#pragma unroll
            for (int j = 0; j < 8; j++) {
                int wi = ((rw[buf][i] >> (4 * j)) & 0xF) - z;
                vals[j] = __hmul(__int2half_rn(wi), s);
            }
            *reinterpret_cast<uint4*>(base + i * 16) =
                *reinterpret_cast<const uint4*>(vals);
        }
    };

    auto compute = [&](int c) {
        uint32_t abase = sbase + (c % 3) * A_STAGE;
        uint32_t bbase = sbase + A_SM3 + (c & 1) * B_STAGE;
        const uint32_t arow = warpM * 64 + (lane & 15);
        const uint32_t brow = warpN * 32 + (lane & 15);
        const uint32_t khalf = (lane >> 4) << 4;   // 0 or 16 bytes
#pragma unroll
        for (int kk = 0; kk < 4; kk++) {
            uint32_t a[4][4];
#pragma unroll
            for (int fm = 0; fm < 4; fm++)
                ldmx4(a[fm], abase + (arow + fm * 16) * ROWB + kk * 32 + khalf);
            uint32_t q[2][4];
#pragma unroll
            for (int nb = 0; nb < 2; nb++)
                ldmx4(q[nb], bbase + (brow + nb * 16) * ROWB + kk * 32 + khalf);
#pragma unroll
            for (int fm = 0; fm < 4; fm++)
#pragma unroll
                for (int nb = 0; nb < 2; nb++) {
                    mma16816(acc[fm][nb * 2],     a[fm], q[nb][0], q[nb][2]);
                    mma16816(acc[fm][nb * 2 + 1], a[fm], q[nb][1], q[nb][3]);
                }
        }
    };

    // ---- prologue: A chunks 0,1 in flight; B chunk0 in smem, chunk1 in regs ----
    issueA(0, 0);
    asm volatile("cp.async.commit_group;");
    issueA(1, 1);
    asm volatile("cp.async.commit_group;");
    ldgB(0, 0);
    stsB(0, 0);
    ldgB(1, 1);

    // ---- mainloop ----
#pragma unroll 1
    for (int c = 0; c < NC; c++) {
        asm volatile("cp.async.wait_group 1;");
        __syncthreads();                       // stage c A ready; stsB(c) visible
        if (c + 2 < NC) {
            issueA((c + 2) % 3, c + 2);        // stage (c-1)%3: readers done
            ldgB(c & 1, c + 2);                // buf of chunk c: sts'd last iter
        }
        asm volatile("cp.async.commit_group;");
        compute(c);
        if (c + 1 < NC) stsB((c + 1) & 1, (c + 1) & 1);
    }

    // ---- epilogue: fp16(sum) + fp16(bias), store f32 ----
    const int ri = lane >> 2;
    const int ci = (lane & 3) * 2;
#pragma unroll
    for (int fn = 0; fn < 4; fn++) {
        int n = bn + warpN * 32 + fn * 8 + ci;
        __half b0 = __float2half_rn(biasf[n]);
        __half b1 = __float2half_rn(biasf[n + 1]);
#pragma unroll
        for (int fm = 0; fm < 4; fm++) {
            int m = bm + warpM * 64 + fm * 16 + ri;
            float2 v0, v1;
            v0.x = __half2float(__hadd(__float2half_rn(acc[fm][fn][0]), b0));
            v0.y = __half2float(__hadd(__float2half_rn(acc[fm][fn][1]), b1));
            v1.x = __half2float(__hadd(__float2half_rn(acc[fm][fn][2]), b0));
            v1.y = __half2float(__hadd(__float2half_rn(acc[fm][fn][3]), b1));
            *reinterpret_cast<float2*>(&out[(size_t)m * N_DIM + n]) = v0;
            *reinterpret_cast<float2*>(&out[(size_t)(m + 8) * N_DIM + n]) = v1;
        }
    }
}

extern "C" void kernel_launch(void* const* d_in, const int* in_sizes, int n_in,
                              void* d_out, int out_size) {
    const float* x       = (const float*)d_in[0];
    const int*   qweight = (const int*)d_in[1];
    const float* scales  = (const float*)d_in[2];
    const int*   qzeros  = (const int*)d_in[3];
    // d_in[4] = g_idx: k/128, folded into indexing
    const float* bias    = (const float*)d_in[5];
    float* out = (float*)d_out;

    convert_x_kernel<<<((size_t)M_DIM * K_DIM) / (256 * 8), 256>>>(x);

    cudaFuncSetAttribute(gemm_fused, cudaFuncAttributeMaxDynamicSharedMemorySize, SMEM_TOTAL);
    dim3 grid(N_DIM / BN, M_DIM / BM);
    gemm_fused<<<grid, THREADS, SMEM_TOTAL>>>(qweight, scales, qzeros, bias, out);
}

// round 8
// speedup vs baseline: 1.9135x; 1.9135x over previous
#include <cuda_runtime.h>
#include <cuda_fp16.h>
#include <cstdint>

#define K_DIM 4096
#define N_DIM 4096
#define M_DIM 8192

#define BM 128
#define BN 128
#define BKC 64
#define NC (K_DIM / BKC)        // 64 chunks
#define THREADS 256

#define ROWB 144                // 64 halves (128B) + 16B pad per smem row
#define A_STAGE (BM * ROWB)     // 18432
#define B_STAGE (BN * ROWB)     // 18432
#define A_SM3 (3 * A_STAGE)     // 55296
#define SMEM_TOTAL (A_SM3 + 3 * B_STAGE)  // 110592 -> 2 CTAs/SM (216KB/228KB)

// x converted fp32 -> fp16 (exact: values originated as fp16).
__device__ __half g_X[(size_t)M_DIM * K_DIM];

__device__ __forceinline__ uint32_t smem_u32(const void* p) {
    return (uint32_t)__cvta_generic_to_shared(p);
}
__device__ __forceinline__ void cp_async16(uint32_t dst, const void* src) {
    asm volatile("cp.async.cg.shared.global [%0], [%1], 16;" :: "r"(dst), "l"(src));
}
__device__ __forceinline__ void ldmx4(uint32_t* r, uint32_t addr) {
    asm volatile("ldmatrix.sync.aligned.m8n8.x4.shared.b16 {%0,%1,%2,%3}, [%4];"
                 : "=r"(r[0]), "=r"(r[1]), "=r"(r[2]), "=r"(r[3]) : "r"(addr));
}
__device__ __forceinline__ void mma16816(float* c, const uint32_t* a, uint32_t b0, uint32_t b1) {
    asm volatile(
        "mma.sync.aligned.m16n8k16.row.col.f32.f16.f16.f32 "
        "{%0,%1,%2,%3}, {%4,%5,%6,%7}, {%8,%9}, {%0,%1,%2,%3};"
        : "+f"(c[0]), "+f"(c[1]), "+f"(c[2]), "+f"(c[3])
        : "r"(a[0]), "r"(a[1]), "r"(a[2]), "r"(a[3]), "r"(b0), "r"(b1));
}

// ---------------- Kernel 0: x fp32 -> fp16 ----------------
__global__ __launch_bounds__(256) void convert_x_kernel(const float* __restrict__ xf) {
    size_t i = ((size_t)blockIdx.x * blockDim.x + threadIdx.x) * 8;
    float4 v0 = *reinterpret_cast<const float4*>(xf + i);
    float4 v1 = *reinterpret_cast<const float4*>(xf + i + 4);
    __half h[8];
    h[0] = __float2half_rn(v0.x); h[1] = __float2half_rn(v0.y);
    h[2] = __float2half_rn(v0.z); h[3] = __float2half_rn(v0.w);
    h[4] = __float2half_rn(v1.x); h[5] = __float2half_rn(v1.y);
    h[6] = __float2half_rn(v1.z); h[7] = __float2half_rn(v1.w);
    *reinterpret_cast<uint4*>(&g_X[i]) = *reinterpret_cast<const uint4*>(h);
}

// ---------------- Kernel 1: fused dequant + GEMM ----------------
// CTA tile 128x128xK64, 256 threads, 8 warps = 2(M) x 4(N), warp tile 64x32.
// 2 CTAs/SM. A: 3-stage cp.async. B: 3-stage, inline 4-bit LDG->unpack->STS
// (no persistent registers; LDG latency hidden by other warps' MMAs).
__global__ __launch_bounds__(THREADS, 2) void gemm_fused(const int* __restrict__ qw,
                                                         const float* __restrict__ scales,
                                                         const int* __restrict__ qz,
                                                         const float* __restrict__ biasf,
                                                         float* __restrict__ out) {
    extern __shared__ __align__(1024) char smem[];
    const uint32_t sbase = smem_u32(smem);
    const int tid = threadIdx.x;
    const int lane = tid & 31;
    const int warp = tid >> 5;
    const int warpM = warp & 1;   // 0..1
    const int warpN = warp >> 1;  // 0..3
    const int bm = blockIdx.y * BM;
    const int bn = blockIdx.x * BN;

    float acc[4][4][4];
#pragma unroll
    for (int i = 0; i < 4; i++)
#pragma unroll
        for (int j = 0; j < 4; j++)
#pragma unroll
            for (int e = 0; e < 4; e++) acc[i][j][e] = 0.0f;

    // ---- A loader: 128 rows x 128B = 1024 16B vectors per stage ----
    auto issueA = [&](int st, int c) {
#pragma unroll
        for (int i = 0; i < 4; i++) {
            int id = tid + i * THREADS;      // 0..1023
            int row = id >> 3;               // 0..127
            int v = id & 7;                  // 0..7
            uint32_t dst = sbase + st * A_STAGE + row * ROWB + v * 16;
            const __half* src = g_X + (size_t)(bm + row) * K_DIM + c * BKC + v * 8;
            cp_async16(dst, src);
        }
    };

    // ---- B: col = tid&127 owns n = bn+col; half = tid>>7 does 4 of the 8
    //      qweight words per chunk. LDG -> unpack -> STS inline. ----
    const int colB = tid & 127;
    const int halfB = tid >> 7;              // 0 or 1
    const int n_own = bn + colB;
    auto loadB = [&](int st, int c) {
        int rw[4];
#pragma unroll
        for (int j = 0; j < 4; j++)
            rw[j] = qw[(size_t)(c * 8 + halfB * 4 + j) * N_DIM + n_own];
        int g = c >> 1;                       // group = (c*64)/128
        __half s = __float2half_rn(scales[g * N_DIM + n_own]);
        int z = ((qz[g * (N_DIM / 8) + (n_own >> 3)] >> ((n_own & 7) * 4)) & 0xF) + 1;
        char* base = smem + A_SM3 + st * B_STAGE + colB * ROWB + halfB * 64;
#pragma unroll
        for (int i = 0; i < 4; i++) {
            __half vals[8];
#pragma unroll
            for (int j = 0; j < 8; j++) {
                int wi = ((rw[i] >> (4 * j)) & 0xF) - z;
                vals[j] = __hmul(__int2half_rn(wi), s);
            }
            *reinterpret_cast<uint4*>(base + i * 16) =
                *reinterpret_cast<const uint4*>(vals);
        }
    };

    auto compute = [&](int c) {
        uint32_t abase = sbase + (c % 3) * A_STAGE;
        uint32_t bbase = sbase + A_SM3 + (c % 3) * B_STAGE;
        const uint32_t arow = warpM * 64 + (lane & 15);
        const uint32_t brow = warpN * 32 + (lane & 15);
        const uint32_t khalf = (lane >> 4) << 4;   // 0 or 16 bytes
#pragma unroll
        for (int kk = 0; kk < 4; kk++) {
            uint32_t a[4][4];
#pragma unroll
            for (int fm = 0; fm < 4; fm++)
                ldmx4(a[fm], abase + (arow + fm * 16) * ROWB + kk * 32 + khalf);
            uint32_t q[2][4];
#pragma unroll
            for (int nb = 0; nb < 2; nb++)
                ldmx4(q[nb], bbase + (brow + nb * 16) * ROWB + kk * 32 + khalf);
#pragma unroll
            for (int fm = 0; fm < 4; fm++)
#pragma unroll
                for (int nb = 0; nb < 2; nb++) {
                    mma16816(acc[fm][nb * 2],     a[fm], q[nb][0], q[nb][2]);
                    mma16816(acc[fm][nb * 2 + 1], a[fm], q[nb][1], q[nb][3]);
                }
        }
    };

    // ---- prologue: A chunks 0,1 in flight; B chunks 0,1 in smem stages 0,1 ----
    issueA(0, 0);
    asm volatile("cp.async.commit_group;");
    issueA(1, 1);
    asm volatile("cp.async.commit_group;");
    loadB(0, 0);
    loadB(1, 1);

    // ---- mainloop: all producer writes hit stage (c+2)%3 == (c-1)%3, whose
    //      readers (compute(c-1)) finished before this iteration's barrier. ----
#pragma unroll 1
    for (int c = 0; c < NC; c++) {
        asm volatile("cp.async.wait_group 1;");
        __syncthreads();                      // A stage c%3 ready; B stores visible
        if (c + 2 < NC) {
            issueA((c + 2) % 3, c + 2);
            asm volatile("cp.async.commit_group;");
            loadB((c + 2) % 3, c + 2);
        } else {
            asm volatile("cp.async.commit_group;");
        }
        compute(c);
    }

    // ---- epilogue: fp16(sum) + fp16(bias), store f32 ----
    const int ri = lane >> 2;
    const int ci = (lane & 3) * 2;
#pragma unroll
    for (int fn = 0; fn < 4; fn++) {
        int n = bn + warpN * 32 + fn * 8 + ci;
        __half b0 = __float2half_rn(biasf[n]);
        __half b1 = __float2half_rn(biasf[n + 1]);
#pragma unroll
        for (int fm = 0; fm < 4; fm++) {
            int m = bm + warpM * 64 + fm * 16 + ri;
            float2 v0, v1;
            v0.x = __half2float(__hadd(__float2half_rn(acc[fm][fn][0]), b0));
            v0.y = __half2float(__hadd(__float2half_rn(acc[fm][fn][1]), b1));
            v1.x = __half2float(__hadd(__float2half_rn(acc[fm][fn][2]), b0));
            v1.y = __half2float(__hadd(__float2half_rn(acc[fm][fn][3]), b1));
            *reinterpret_cast<float2*>(&out[(size_t)m * N_DIM + n]) = v0;
            *reinterpret_cast<float2*>(&out[(size_t)(m + 8) * N_DIM + n]) = v1;
        }
    }
}

extern "C" void kernel_launch(void* const* d_in, const int* in_sizes, int n_in,
                              void* d_out, int out_size) {
    const float* x       = (const float*)d_in[0];
    const int*   qweight = (const int*)d_in[1];
    const float* scales  = (const float*)d_in[2];
    const int*   qzeros  = (const int*)d_in[3];
    // d_in[4] = g_idx: k/128, folded into indexing
    const float* bias    = (const float*)d_in[5];
    float* out = (float*)d_out;

    convert_x_kernel<<<((size_t)M_DIM * K_DIM) / (256 * 8), 256>>>(x);

    cudaFuncSetAttribute(gemm_fused, cudaFuncAttributeMaxDynamicSharedMemorySize, SMEM_TOTAL);
    dim3 grid(N_DIM / BN, M_DIM / BM);
    gemm_fused<<<grid, THREADS, SMEM_TOTAL>>>(qweight, scales, qzeros, bias, out);
}

// round 9
// speedup vs baseline: 1.9302x; 1.0087x over previous
#include <cuda_runtime.h>
#include <cuda_fp16.h>
#include <cstdint>

#define K_DIM 4096
#define N_DIM 4096
#define M_DIM 8192

#define BM 128
#define BN 128
#define BKC 64
#define NC (K_DIM / BKC)        // 64 chunks
#define THREADS 256

#define ROWB 144                // 64 halves (128B) + 16B pad per smem row
#define A_STAGE (BM * ROWB)     // 18432
#define B_STAGE (BN * ROWB)     // 18432
#define A_SM3 (3 * A_STAGE)     // 55296
#define SMEM_TOTAL (A_SM3 + 3 * B_STAGE)  // 110592 -> 2 CTAs/SM (216KB/228KB)

// Dequantized weights [N][K], K contiguous (col-major B for row.col MMA).
__device__ __half g_W[(size_t)N_DIM * K_DIM];
// x converted fp32 -> fp16 (exact: values originated as fp16).
__device__ __half g_X[(size_t)M_DIM * K_DIM];

__device__ __forceinline__ uint32_t smem_u32(const void* p) {
    return (uint32_t)__cvta_generic_to_shared(p);
}
__device__ __forceinline__ void cp_async16(uint32_t dst, const void* src) {
    asm volatile("cp.async.cg.shared.global [%0], [%1], 16;" :: "r"(dst), "l"(src));
}
__device__ __forceinline__ void ldmx4(uint32_t* r, uint32_t addr) {
    asm volatile("ldmatrix.sync.aligned.m8n8.x4.shared.b16 {%0,%1,%2,%3}, [%4];"
                 : "=r"(r[0]), "=r"(r[1]), "=r"(r[2]), "=r"(r[3]) : "r"(addr));
}
__device__ __forceinline__ void mma16816(float* c, const uint32_t* a, uint32_t b0, uint32_t b1) {
    asm volatile(
        "mma.sync.aligned.m16n8k16.row.col.f32.f16.f16.f32 "
        "{%0,%1,%2,%3}, {%4,%5,%6,%7}, {%8,%9}, {%0,%1,%2,%3};"
        : "+f"(c[0]), "+f"(c[1]), "+f"(c[2]), "+f"(c[3])
        : "r"(a[0]), "r"(a[1]), "r"(a[2]), "r"(a[3]), "r"(b0), "r"(b1));
}

// ---------------- Kernel 0: x fp32 -> fp16 ----------------
__global__ __launch_bounds__(256) void convert_x_kernel(const float* __restrict__ xf) {
    size_t i = ((size_t)blockIdx.x * blockDim.x + threadIdx.x) * 8;
    float4 v0 = *reinterpret_cast<const float4*>(xf + i);
    float4 v1 = *reinterpret_cast<const float4*>(xf + i + 4);
    __half h[8];
    h[0] = __float2half_rn(v0.x); h[1] = __float2half_rn(v0.y);
    h[2] = __float2half_rn(v0.z); h[3] = __float2half_rn(v0.w);
    h[4] = __float2half_rn(v1.x); h[5] = __float2half_rn(v1.y);
    h[6] = __float2half_rn(v1.z); h[7] = __float2half_rn(v1.w);
    *reinterpret_cast<uint4*>(&g_X[i]) = *reinterpret_cast<const uint4*>(h);
}

// ---------------- Kernel 1: GPTQ 4-bit dequant -> g_W ----------------
__global__ __launch_bounds__(256) void dequant_kernel(const int* __restrict__ qw,
                                                      const float* __restrict__ scales,
                                                      const int* __restrict__ qz) {
    int idx = blockIdx.x * blockDim.x + threadIdx.x;
    int r = idx & 511;          // K_DIM/8 rows of qweight
    int n = idx >> 9;
    int w = qw[r * N_DIM + n];
    int g = r >> 4;             // (r*8)/128
    int zw = qz[g * (N_DIM / 8) + (n >> 3)];
    int z = ((zw >> ((n & 7) * 4)) & 0xF) + 1;
    __half s = __float2half_rn(scales[g * N_DIM + n]);
    __half vals[8];
#pragma unroll
    for (int j = 0; j < 8; j++) {
        int wi = ((w >> (4 * j)) & 0xF) - z;
        vals[j] = __hmul(__int2half_rn(wi), s);
    }
    *reinterpret_cast<uint4*>(&g_W[(size_t)n * K_DIM + r * 8]) =
        *reinterpret_cast<const uint4*>(vals);
}

// ---------------- Kernel 2: GEMM ----------------
// CTA tile 128x128xK64, 256 threads, 8 warps = 2(M) x 4(N), warp tile 64x32.
// 2 CTAs/SM. A and B both 3-stage cp.async (B from pre-dequantized g_W).
__global__ __launch_bounds__(THREADS, 2) void gemm_kernel(const float* __restrict__ biasf,
                                                          float* __restrict__ out) {
    extern __shared__ __align__(1024) char smem[];
    const uint32_t sbase = smem_u32(smem);
    const int tid = threadIdx.x;
    const int lane = tid & 31;
    const int warp = tid >> 5;
    const int warpM = warp & 1;   // 0..1
    const int warpN = warp >> 1;  // 0..3
    const int bm = blockIdx.y * BM;
    const int bn = blockIdx.x * BN;

    float acc[4][4][4];
#pragma unroll
    for (int i = 0; i < 4; i++)
#pragma unroll
        for (int j = 0; j < 4; j++)
#pragma unroll
            for (int e = 0; e < 4; e++) acc[i][j][e] = 0.0f;

    // ---- stage loader: A and B are symmetric 128x128B tiles ----
    auto issueStage = [&](int st, int c) {
        const __half* asrc = g_X + (size_t)bm * K_DIM + c * BKC;
        const __half* bsrc = g_W + (size_t)bn * K_DIM + c * BKC;
#pragma unroll
        for (int i = 0; i < 4; i++) {
            int id = tid + i * THREADS;      // 0..1023
            int row = id >> 3;               // 0..127
            int v = id & 7;                  // 0..7
            cp_async16(sbase + st * A_STAGE + row * ROWB + v * 16,
                       asrc + (size_t)row * K_DIM + v * 8);
            cp_async16(sbase + A_SM3 + st * B_STAGE + row * ROWB + v * 16,
                       bsrc + (size_t)row * K_DIM + v * 8);
        }
        asm volatile("cp.async.commit_group;");
    };

    auto compute = [&](int c) {
        uint32_t abase = sbase + (c % 3) * A_STAGE;
        uint32_t bbase = sbase + A_SM3 + (c % 3) * B_STAGE;
        const uint32_t arow = warpM * 64 + (lane & 15);
        const uint32_t brow = warpN * 32 + (lane & 15);
        const uint32_t khalf = (lane >> 4) << 4;   // 0 or 16 bytes
#pragma unroll
        for (int kk = 0; kk < 4; kk++) {
            uint32_t a[4][4];
#pragma unroll
            for (int fm = 0; fm < 4; fm++)
                ldmx4(a[fm], abase + (arow + fm * 16) * ROWB + kk * 32 + khalf);
            uint32_t q[2][4];
#pragma unroll
            for (int nb = 0; nb < 2; nb++)
                ldmx4(q[nb], bbase + (brow + nb * 16) * ROWB + kk * 32 + khalf);
#pragma unroll
            for (int fm = 0; fm < 4; fm++)
#pragma unroll
                for (int nb = 0; nb < 2; nb++) {
                    mma16816(acc[fm][nb * 2],     a[fm], q[nb][0], q[nb][2]);
                    mma16816(acc[fm][nb * 2 + 1], a[fm], q[nb][1], q[nb][3]);
                }
        }
    };

    // ---- prologue: chunks 0,1 in flight ----
    issueStage(0, 0);
    issueStage(1, 1);

    // ---- mainloop: producer writes hit stage (c+2)%3 == (c-1)%3, whose
    //      readers finished before this iteration's barrier. ----
#pragma unroll 1
    for (int c = 0; c < NC; c++) {
        asm volatile("cp.async.wait_group 1;");
        __syncthreads();                      // stage c%3 ready
        if (c + 2 < NC) {
            issueStage((c + 2) % 3, c + 2);
        } else {
            asm volatile("cp.async.commit_group;");
        }
        compute(c);
    }

    // ---- epilogue: fp16(sum) + fp16(bias), store f32 ----
    const int ri = lane >> 2;
    const int ci = (lane & 3) * 2;
#pragma unroll
    for (int fn = 0; fn < 4; fn++) {
        int n = bn + warpN * 32 + fn * 8 + ci;
        __half b0 = __float2half_rn(biasf[n]);
        __half b1 = __float2half_rn(biasf[n + 1]);
#pragma unroll
        for (int fm = 0; fm < 4; fm++) {
            int m = bm + warpM * 64 + fm * 16 + ri;
            float2 v0, v1;
            v0.x = __half2float(__hadd(__float2half_rn(acc[fm][fn][0]), b0));
            v0.y = __half2float(__hadd(__float2half_rn(acc[fm][fn][1]), b1));
            v1.x = __half2float(__hadd(__float2half_rn(acc[fm][fn][2]), b0));
            v1.y = __half2float(__hadd(__float2half_rn(acc[fm][fn][3]), b1));
            *reinterpret_cast<float2*>(&out[(size_t)m * N_DIM + n]) = v0;
            *reinterpret_cast<float2*>(&out[(size_t)(m + 8) * N_DIM + n]) = v1;
        }
    }
}

extern "C" void kernel_launch(void* const* d_in, const int* in_sizes, int n_in,
                              void* d_out, int out_size) {
    const float* x       = (const float*)d_in[0];
    const int*   qweight = (const int*)d_in[1];
    const float* scales  = (const float*)d_in[2];
    const int*   qzeros  = (const int*)d_in[3];
    // d_in[4] = g_idx: k/128, folded into dequant indexing
    const float* bias    = (const float*)d_in[5];
    float* out = (float*)d_out;

    convert_x_kernel<<<((size_t)M_DIM * K_DIM) / (256 * 8), 256>>>(x);
    dequant_kernel<<<(512 * N_DIM) / 256, 256>>>(qweight, scales, qzeros);

    cudaFuncSetAttribute(gemm_kernel, cudaFuncAttributeMaxDynamicSharedMemorySize, SMEM_TOTAL);
    dim3 grid(N_DIM / BN, M_DIM / BM);
    gemm_kernel<<<grid, THREADS, SMEM_TOTAL>>>(bias, out);
}